// round 1
// baseline (speedup 1.0000x reference)
#include <cuda_runtime.h>
#include <cuda_bf16.h>
#include <math.h>

// ---------------------------------------------------------------------------
// GAT: 3 layers. Per layer:
//   h   = x @ W            (N x H*C)
//   lin = x @ lw           (N x outF)
//   alpha_s/alpha_d = per-(node,head) dot(h, a)
//   edge pass A: m[dst,h]   = max leaky_relu(as[src]+ad[dst])
//   edge pass B: den[dst,h] = sum exp(e - m)
//   edge pass C: acc[dst]  += h[src] * exp(e-m)/den
//   finalize: concat layers -> elu(acc + b + lin + lb); last -> mean heads + b + lin + lb
// ---------------------------------------------------------------------------

#define MAXN 20000

__device__ float g_h[MAXN * 1536];
__device__ float g_lin[MAXN * 1024];
__device__ float g_o1[MAXN * 1024];
__device__ float g_o2[MAXN * 1024];
__device__ float g_acc[MAXN * 1536];
__device__ float g_as[MAXN * 6];
__device__ float g_ad[MAXN * 6];
__device__ float g_m[MAXN * 6];
__device__ float g_den[MAXN * 6];

// ------------------------------ SGEMM --------------------------------------
// C[M,N] = A[M,K] @ B[K,N], row-major. BM=BN=128, BK=16, 256 thr, 8x8/thread.
// N % 128 == 0 and K % 16 == 0 are guaranteed by the problem shapes.
#define BM 128
#define BN 128
#define BK 16
#define TM 8
#define TN 8

__global__ __launch_bounds__(256) void sgemm_kernel(
    const float* __restrict__ A, const float* __restrict__ B,
    float* __restrict__ C, int M, int N, int K)
{
    __shared__ float As[BK][BM];
    __shared__ float Bs[BK][BN];

    const int tid = threadIdx.x;
    const int blockRow = blockIdx.y * BM;
    const int blockCol = blockIdx.x * BN;

    const int tRow = (tid / 16) * TM;
    const int tCol = (tid % 16) * TN;

    float acc[TM][TN];
#pragma unroll
    for (int i = 0; i < TM; i++)
#pragma unroll
        for (int j = 0; j < TN; j++) acc[i][j] = 0.f;

    const int aRow  = tid / 4;         // 0..63  (+64 for second load)
    const int aCol4 = (tid % 4) * 4;   // 0,4,8,12
    const int bRow  = tid / 32;        // 0..7   (+8 for second load)
    const int bCol4 = (tid % 32) * 4;

    for (int k0 = 0; k0 < K; k0 += BK) {
#pragma unroll
        for (int r = 0; r < 2; r++) {
            int row = blockRow + aRow + r * 64;
            float4 v;
            if (row < M) v = *(const float4*)&A[(size_t)row * K + k0 + aCol4];
            else         v = make_float4(0.f, 0.f, 0.f, 0.f);
            As[aCol4 + 0][aRow + r * 64] = v.x;
            As[aCol4 + 1][aRow + r * 64] = v.y;
            As[aCol4 + 2][aRow + r * 64] = v.z;
            As[aCol4 + 3][aRow + r * 64] = v.w;
        }
#pragma unroll
        for (int r = 0; r < 2; r++) {
            int row = k0 + bRow + r * 8;
            *(float4*)&Bs[bRow + r * 8][bCol4] =
                *(const float4*)&B[(size_t)row * N + blockCol + bCol4];
        }
        __syncthreads();

#pragma unroll
        for (int kk = 0; kk < BK; kk++) {
            float ra[TM], rb[TN];
#pragma unroll
            for (int i = 0; i < TM; i++) ra[i] = As[kk][tRow + i];
#pragma unroll
            for (int j = 0; j < TN; j++) rb[j] = Bs[kk][tCol + j];
#pragma unroll
            for (int i = 0; i < TM; i++)
#pragma unroll
                for (int j = 0; j < TN; j++)
                    acc[i][j] += ra[i] * rb[j];
        }
        __syncthreads();
    }

#pragma unroll
    for (int i = 0; i < TM; i++) {
        int row = blockRow + tRow + i;
        if (row < M) {
#pragma unroll
            for (int j = 0; j < TN; j += 4) {
                *(float4*)&C[(size_t)row * N + blockCol + tCol + j] =
                    make_float4(acc[i][j], acc[i][j + 1], acc[i][j + 2], acc[i][j + 3]);
            }
        }
    }
}

// ------------------------------ helpers ------------------------------------

__global__ void fill_kernel(float* __restrict__ p, float v, int n)
{
    int i = blockIdx.x * blockDim.x + threadIdx.x;
    if (i < n) p[i] = v;
}

// per-(node,head) attention logits: one warp per (node,head)
__global__ void alpha_kernel(const float* __restrict__ h,
                             const float* __restrict__ a_s,
                             const float* __restrict__ a_d,
                             float* __restrict__ as_out,
                             float* __restrict__ ad_out,
                             int n, int H, int C)
{
    int warp = (blockIdx.x * blockDim.x + threadIdx.x) >> 5;
    int lane = threadIdx.x & 31;
    if (warp >= n * H) return;
    int node = warp / H;
    int head = warp - node * H;
    const float* hp  = h + (size_t)node * H * C + head * C;
    const float* asp = a_s + head * C;
    const float* adp = a_d + head * C;
    float s = 0.f, d = 0.f;
    for (int c = lane; c < C; c += 32) {
        float hv = hp[c];
        s += hv * asp[c];
        d += hv * adp[c];
    }
#pragma unroll
    for (int o = 16; o; o >>= 1) {
        s += __shfl_down_sync(0xffffffffu, s, o);
        d += __shfl_down_sync(0xffffffffu, d, o);
    }
    if (lane == 0) {
        as_out[node * H + head] = s;
        ad_out[node * H + head] = d;
    }
}

__device__ __forceinline__ void atomicMaxF(float* addr, float val)
{
    int old = __float_as_int(*addr);
    while (__int_as_float(old) < val) {
        int assumed = old;
        old = atomicCAS((int*)addr, assumed, __float_as_int(val));
        if (old == assumed) break;
    }
}

__device__ __forceinline__ float leaky02(float v)
{
    return v > 0.f ? v : 0.2f * v;
}

__global__ void edge_max_kernel(const int* __restrict__ ei, int E, int n,
                                const float* __restrict__ as,
                                const float* __restrict__ ad,
                                float* __restrict__ m, int H)
{
    int e = blockIdx.x * blockDim.x + threadIdx.x;
    if (e >= E + n) return;
    int s = (e < E) ? ei[e]     : (e - E);
    int d = (e < E) ? ei[E + e] : (e - E);
    for (int h = 0; h < H; h++) {
        float v = leaky02(as[s * H + h] + ad[d * H + h]);
        atomicMaxF(&m[d * H + h], v);
    }
}

__global__ void edge_sum_kernel(const int* __restrict__ ei, int E, int n,
                                const float* __restrict__ as,
                                const float* __restrict__ ad,
                                const float* __restrict__ m,
                                float* __restrict__ den, int H)
{
    int e = blockIdx.x * blockDim.x + threadIdx.x;
    if (e >= E + n) return;
    int s = (e < E) ? ei[e]     : (e - E);
    int d = (e < E) ? ei[E + e] : (e - E);
    for (int h = 0; h < H; h++) {
        float v = leaky02(as[s * H + h] + ad[d * H + h]);
        atomicAdd(&den[d * H + h], __expf(v - m[d * H + h]));
    }
}

// one block per edge; scatter h[src]*coef into acc[dst]
__global__ __launch_bounds__(256) void edge_scatter_kernel(
    const int* __restrict__ ei, int E, int n,
    const float* __restrict__ as, const float* __restrict__ ad,
    const float* __restrict__ m, const float* __restrict__ den,
    const float* __restrict__ h, float* __restrict__ acc,
    int H, int C)
{
    int e = blockIdx.x;
    int s = (e < E) ? ei[e]     : (e - E);
    int d = (e < E) ? ei[E + e] : (e - E);

    __shared__ float coef[8];
    if (threadIdx.x < H) {
        int hh = threadIdx.x;
        float v = leaky02(as[s * H + hh] + ad[d * H + hh]);
        coef[hh] = __expf(v - m[d * H + hh]) / (den[d * H + hh] + 1e-16f);
    }
    __syncthreads();

    int HC = H * C;
    const float4* hs = (const float4*)(h + (size_t)s * HC);
    float* ap = acc + (size_t)d * HC;
    for (int i = threadIdx.x; i < HC / 4; i += blockDim.x) {
        float4 v = hs[i];
        float c = coef[(i * 4) >> 8];   // C == 256
        atomicAdd(&ap[i * 4 + 0], v.x * c);
        atomicAdd(&ap[i * 4 + 1], v.y * c);
        atomicAdd(&ap[i * 4 + 2], v.z * c);
        atomicAdd(&ap[i * 4 + 3], v.w * c);
    }
}

// layers 1,2: out = elu(acc + b + lin + lb), HC = 1024
__global__ void finalize_cat_kernel(const float* __restrict__ acc,
                                    const float* __restrict__ lin,
                                    const float* __restrict__ b,
                                    const float* __restrict__ lb,
                                    float* __restrict__ out, int n, int HC)
{
    int i = blockIdx.x * blockDim.x + threadIdx.x;
    if (i >= n * HC) return;
    int col = i % HC;
    float v = acc[i] + b[col] + lin[i] + lb[col];
    out[i] = v > 0.f ? v : expm1f(v);
}

// layer 3: out = mean_heads(acc) + b + lin + lb   (C = 256)
__global__ void finalize_mean_kernel(const float* __restrict__ acc,
                                     const float* __restrict__ lin,
                                     const float* __restrict__ b,
                                     const float* __restrict__ lb,
                                     float* __restrict__ out,
                                     int rows, int H, int C)
{
    int i = blockIdx.x * blockDim.x + threadIdx.x;
    if (i >= rows * C) return;
    int nrow = i / C;
    int c = i - nrow * C;
    const float* ap = acc + (size_t)nrow * H * C + c;
    float s = 0.f;
    for (int h = 0; h < H; h++) s += ap[h * C];
    out[i] = s * (1.f / H) + b[c] + lin[(size_t)nrow * C + c] + lb[c];
}

// ------------------------------ host orchestration -------------------------

static void run_gat_layer(const float* xin, int inCh,
                          const float* W, const float* aS, const float* aD,
                          const float* bias, const float* lw, const float* lb,
                          int H, int C, float* outBuf, bool last,
                          int n, int E, int rows_out,
                          float* hbuf, float* linbuf, float* accbuf,
                          float* asbuf, float* adbuf, float* mbuf, float* denbuf)
{
    const int HC = H * C;
    const int linN = last ? C : 1024;
    const int total_e = E + n;

    dim3 g1(HC / BN, (n + BM - 1) / BM);
    sgemm_kernel<<<g1, 256>>>(xin, W, hbuf, n, HC, inCh);

    dim3 g2(linN / BN, (n + BM - 1) / BM);
    sgemm_kernel<<<g2, 256>>>(xin, lw, linbuf, n, linN, inCh);

    alpha_kernel<<<(n * H * 32 + 255) / 256, 256>>>(hbuf, aS, aD, asbuf, adbuf, n, H, C);

    fill_kernel<<<(n * H + 255) / 256, 256>>>(mbuf, -INFINITY, n * H);
    fill_kernel<<<(n * H + 255) / 256, 256>>>(denbuf, 0.f, n * H);
    fill_kernel<<<(n * HC + 255) / 256, 256>>>(accbuf, 0.f, n * HC);

    const int* ei_dummy = nullptr; // set by caller via global below
    (void)ei_dummy;
    // edge index pointer passed through static below (set in kernel_launch)
    extern const int* g_ei_host;
    edge_max_kernel<<<(total_e + 255) / 256, 256>>>(g_ei_host, E, n, asbuf, adbuf, mbuf, H);
    edge_sum_kernel<<<(total_e + 255) / 256, 256>>>(g_ei_host, E, n, asbuf, adbuf, mbuf, denbuf, H);
    edge_scatter_kernel<<<total_e, 256>>>(g_ei_host, E, n, asbuf, adbuf, mbuf, denbuf,
                                          hbuf, accbuf, H, C);

    if (!last) {
        finalize_cat_kernel<<<(n * HC + 255) / 256, 256>>>(accbuf, linbuf, bias, lb, outBuf, n, HC);
    } else {
        finalize_mean_kernel<<<(rows_out * C + 255) / 256, 256>>>(accbuf, linbuf, bias, lb,
                                                                  outBuf, rows_out, H, C);
    }
}

const int* g_ei_host = nullptr;

extern "C" void kernel_launch(void* const* d_in, const int* in_sizes, int n_in,
                              void* d_out, int out_size)
{
    const float* x   = (const float*)d_in[0];
    const int*   ei  = (const int*)d_in[1];
    // d_in[2] = original_size (derived from out_size instead)
    const float* W1  = (const float*)d_in[3];
    const float* as1 = (const float*)d_in[4];
    const float* ad1 = (const float*)d_in[5];
    const float* b1  = (const float*)d_in[6];
    const float* lw1 = (const float*)d_in[7];
    const float* lb1 = (const float*)d_in[8];
    const float* W2  = (const float*)d_in[9];
    const float* as2 = (const float*)d_in[10];
    const float* ad2 = (const float*)d_in[11];
    const float* b2  = (const float*)d_in[12];
    const float* lw2 = (const float*)d_in[13];
    const float* lb2 = (const float*)d_in[14];
    const float* W3  = (const float*)d_in[15];
    const float* as3 = (const float*)d_in[16];
    const float* ad3 = (const float*)d_in[17];
    const float* b3  = (const float*)d_in[18];
    const float* lw3 = (const float*)d_in[19];
    const float* lb3 = (const float*)d_in[20];

    const int n = in_sizes[0] / 512;
    const int E = in_sizes[1] / 2;
    const int rows_out = out_size / 256;

    g_ei_host = ei;

    float *hbuf, *linbuf, *o1, *o2, *accbuf, *asbuf, *adbuf, *mbuf, *denbuf;
    cudaGetSymbolAddress((void**)&hbuf,   g_h);
    cudaGetSymbolAddress((void**)&linbuf, g_lin);
    cudaGetSymbolAddress((void**)&o1,     g_o1);
    cudaGetSymbolAddress((void**)&o2,     g_o2);
    cudaGetSymbolAddress((void**)&accbuf, g_acc);
    cudaGetSymbolAddress((void**)&asbuf,  g_as);
    cudaGetSymbolAddress((void**)&adbuf,  g_ad);
    cudaGetSymbolAddress((void**)&mbuf,   g_m);
    cudaGetSymbolAddress((void**)&denbuf, g_den);

    // Layer 1: 512 -> 4x256 concat (1024)
    run_gat_layer(x, 512, W1, as1, ad1, b1, lw1, lb1, 4, 256, o1, false,
                  n, E, rows_out, hbuf, linbuf, accbuf, asbuf, adbuf, mbuf, denbuf);
    // Layer 2: 1024 -> 4x256 concat (1024)
    run_gat_layer(o1, 1024, W2, as2, ad2, b2, lw2, lb2, 4, 256, o2, false,
                  n, E, rows_out, hbuf, linbuf, accbuf, asbuf, adbuf, mbuf, denbuf);
    // Layer 3: 1024 -> 6x256 mean (256)
    run_gat_layer(o2, 1024, W3, as3, ad3, b3, lw3, lb3, 6, 256, (float*)d_out, true,
                  n, E, rows_out, hbuf, linbuf, accbuf, asbuf, adbuf, mbuf, denbuf);
}

// round 3
// speedup vs baseline: 1.5162x; 1.5162x over previous
#include <cuda_runtime.h>
#include <cuda_bf16.h>
#include <math.h>
#include <stdint.h>

// ---------------------------------------------------------------------------
// GAT, 3 layers. GEMMs via mma.sync bf16 (hi/lo split, triple-K compensation)
// (tcgen05 unavailable: harness PTX target is compute_103 base, not 103a).
// ---------------------------------------------------------------------------

#define MAXN  20000
#define MAXNP 20096   // padded to multiple of 128

__device__ float g_h[MAXNP * 1536];
__device__ float g_lin[MAXNP * 1024];
__device__ float g_o1[MAXN * 1024];
__device__ float g_o2[MAXN * 1024];
__device__ float g_acc[MAXN * 1536];
__device__ float g_as[MAXN * 6];
__device__ float g_ad[MAXN * 6];
__device__ float g_m[MAXN * 6];
__device__ float g_den[MAXN * 6];

__device__ __align__(256) __nv_bfloat16 g_asplit[(size_t)MAXNP * 3072];
__device__ __align__(256) __nv_bfloat16 g_bsplitW[1536 * 3072];
__device__ __align__(256) __nv_bfloat16 g_bsplitL[1024 * 3072];

// ------------------------- mma.sync bf16 GEMM ------------------------------
// C[M,N] = A[M,K] @ B^T ; A row-major [M,K] bf16, B row-major [N,K] bf16.
// M%128==0, N%128==0, K%64==0.

#define BM 128
#define BN 128
#define BKE 64                 // bf16 elements per k-chunk
#define PITCH 72               // padded row pitch in elements (144 bytes)
#define ROWB (PITCH * 2)       // 144 bytes
#define ASTG (BM * ROWB)       // 18432
#define BSTG (BN * ROWB)       // 18432
#define STG  (ASTG + BSTG)     // 36864
#define NSTG 3
#define GEMM_SMEM (NSTG * STG) // 110592

__device__ __forceinline__ uint32_t smem_u32(const void* p) {
    uint32_t a;
    asm("{ .reg .u64 t; cvta.to.shared.u64 t, %1; cvt.u32.u64 %0, t; }"
        : "=r"(a) : "l"(p));
    return a;
}

__device__ __forceinline__ void cp_async16(uint32_t saddr, const void* gptr) {
    asm volatile("cp.async.cg.shared.global [%0], [%1], 16;" :: "r"(saddr), "l"(gptr));
}
__device__ __forceinline__ void cp_commit() {
    asm volatile("cp.async.commit_group;" ::: "memory");
}
template<int NN> __device__ __forceinline__ void cp_wait() {
    asm volatile("cp.async.wait_group %0;" :: "n"(NN) : "memory");
}

__device__ __forceinline__ void ldmA(uint32_t addr, uint32_t& r0, uint32_t& r1,
                                     uint32_t& r2, uint32_t& r3) {
    asm volatile("ldmatrix.sync.aligned.m8n8.x4.shared.b16 {%0,%1,%2,%3}, [%4];"
                 : "=r"(r0), "=r"(r1), "=r"(r2), "=r"(r3) : "r"(addr));
}
__device__ __forceinline__ void ldmB(uint32_t addr, uint32_t& r0, uint32_t& r1) {
    asm volatile("ldmatrix.sync.aligned.m8n8.x2.shared.b16 {%0,%1}, [%2];"
                 : "=r"(r0), "=r"(r1) : "r"(addr));
}
__device__ __forceinline__ void mma16816(float* c, uint32_t a0, uint32_t a1,
                                         uint32_t a2, uint32_t a3,
                                         uint32_t b0, uint32_t b1) {
    asm volatile(
        "mma.sync.aligned.m16n8k16.row.col.f32.bf16.bf16.f32 "
        "{%0,%1,%2,%3}, {%4,%5,%6,%7}, {%8,%9}, {%0,%1,%2,%3};"
        : "+f"(c[0]), "+f"(c[1]), "+f"(c[2]), "+f"(c[3])
        : "r"(a0), "r"(a1), "r"(a2), "r"(a3), "r"(b0), "r"(b1));
}

__global__ __launch_bounds__(256)
void gemm_bf16_mma_kernel(const __nv_bfloat16* __restrict__ A,
                          const __nv_bfloat16* __restrict__ B,
                          float* __restrict__ C, int M, int N, int K)
{
    extern __shared__ char sm[];
    const uint32_t smb = smem_u32(sm);
    const int tid = threadIdx.x;
    const int lane = tid & 31;
    const int wid = tid >> 5;
    const int wm = wid & 1;        // 0..1
    const int wn = wid >> 1;       // 0..3
    const int rowBase = blockIdx.y * BM;
    const int colBase = blockIdx.x * BN;

    float acc[4][4][4];
#pragma unroll
    for (int i = 0; i < 4; i++)
#pragma unroll
        for (int j = 0; j < 4; j++)
#pragma unroll
            for (int v = 0; v < 4; v++) acc[i][j][v] = 0.f;

    const int nk = K / BKE;

    // issue loads for chunk kc into stage s
    auto issue = [&](int s, int kc) {
        uint32_t aB = smb + s * STG;
        uint32_t bB = aB + ASTG;
#pragma unroll
        for (int g = 0; g < 4; g++) {
            int gi = g * 256 + tid;
            int r = gi >> 3;
            int c = gi & 7;
            const __nv_bfloat16* ga = A + (size_t)(rowBase + r) * K + kc * BKE + c * 8;
            cp_async16(aB + r * ROWB + c * 16, ga);
            const __nv_bfloat16* gb = B + (size_t)(colBase + r) * K + kc * BKE + c * 8;
            cp_async16(bB + r * ROWB + c * 16, gb);
        }
        cp_commit();
    };

    // prologue
#pragma unroll
    for (int s = 0; s < NSTG - 1; s++)
        if (s < nk) issue(s, s);

    const int l16 = lane & 15;
    const int aRowOff = l16;              // row within 16-row tile
    const int aColOff = (lane >> 4) * 16; // byte offset within 32B k16 block
    const int bRowOff = lane & 7;
    const int bColOff = ((lane >> 3) & 1) * 16;

    for (int i = 0; i < nk; i++) {
        cp_wait<NSTG - 2>();
        __syncthreads();
        if (i + NSTG - 1 < nk) issue((i + NSTG - 1) % NSTG, i + NSTG - 1);

        uint32_t aB = smb + (i % NSTG) * STG;
        uint32_t bB = aB + ASTG;
#pragma unroll
        for (int ks = 0; ks < 4; ks++) {
            uint32_t a[4][4], b[4][2];
#pragma unroll
            for (int im = 0; im < 4; im++) {
                int row = wm * 64 + im * 16 + aRowOff;
                ldmA(aB + row * ROWB + ks * 32 + aColOff,
                     a[im][0], a[im][1], a[im][2], a[im][3]);
            }
#pragma unroll
            for (int jn = 0; jn < 4; jn++) {
                int row = wn * 32 + jn * 8 + bRowOff;
                ldmB(bB + row * ROWB + ks * 32 + bColOff, b[jn][0], b[jn][1]);
            }
#pragma unroll
            for (int im = 0; im < 4; im++)
#pragma unroll
                for (int jn = 0; jn < 4; jn++)
                    mma16816(acc[im][jn], a[im][0], a[im][1], a[im][2], a[im][3],
                             b[jn][0], b[jn][1]);
        }
        __syncthreads();
    }

    // epilogue
    const int q = lane >> 2;          // 0..7
    const int qc = (lane & 3) * 2;    // 0,2,4,6
#pragma unroll
    for (int im = 0; im < 4; im++) {
        int r0 = rowBase + wm * 64 + im * 16 + q;
#pragma unroll
        for (int jn = 0; jn < 4; jn++) {
            int col = colBase + wn * 32 + jn * 8 + qc;
            float* p0 = C + (size_t)r0 * N + col;
            float* p1 = C + (size_t)(r0 + 8) * N + col;
            p0[0] = acc[im][jn][0]; p0[1] = acc[im][jn][1];
            p1[0] = acc[im][jn][2]; p1[1] = acc[im][jn][3];
        }
    }
}

// ---------------------- split-bf16 conversion kernels ----------------------
// A: fp32 [n,K] -> bf16 [MP, 3K]: cols [0,K)=hi, [K,2K)=lo, [2K,3K)=hi
__global__ void convert_A_kernel(const float* __restrict__ x,
                                 __nv_bfloat16* __restrict__ out,
                                 int n, int MP, int K)
{
    int idx = blockIdx.x * blockDim.x + threadIdx.x;
    if (idx >= MP * K) return;
    int row = idx / K;
    int k = idx - row * K;
    float a = (row < n) ? x[(size_t)row * K + k] : 0.f;
    __nv_bfloat16 hi = __float2bfloat16(a);
    __nv_bfloat16 lo = __float2bfloat16(a - __bfloat162float(hi));
    size_t base = (size_t)row * (3 * K);
    out[base + k] = hi;
    out[base + K + k] = lo;
    out[base + 2 * K + k] = hi;
}

// B: fp32 [K,Nout] row-major -> bf16 [Nout, 3K] (K-major rows):
// cols [0,K)=hi, [K,2K)=hi, [2K,3K)=lo
__global__ void convert_B_kernel(const float* __restrict__ Bsrc,
                                 __nv_bfloat16* __restrict__ out,
                                 int K, int Nout)
{
    int idx = blockIdx.x * blockDim.x + threadIdx.x;
    if (idx >= K * Nout) return;
    int k = idx / Nout;
    int nn = idx - k * Nout;
    float b = Bsrc[(size_t)k * Nout + nn];
    __nv_bfloat16 hi = __float2bfloat16(b);
    __nv_bfloat16 lo = __float2bfloat16(b - __bfloat162float(hi));
    size_t base = (size_t)nn * (3 * K);
    out[base + k] = hi;
    out[base + K + k] = hi;
    out[base + 2 * K + k] = lo;
}

// ------------------------------ helpers ------------------------------------

__global__ void fill_kernel(float* __restrict__ p, float v, int n)
{
    int i = blockIdx.x * blockDim.x + threadIdx.x;
    if (i < n) p[i] = v;
}

__global__ void alpha_kernel(const float* __restrict__ h,
                             const float* __restrict__ a_s,
                             const float* __restrict__ a_d,
                             float* __restrict__ as_out,
                             float* __restrict__ ad_out,
                             int n, int H, int C)
{
    int warp = (blockIdx.x * blockDim.x + threadIdx.x) >> 5;
    int lane = threadIdx.x & 31;
    if (warp >= n * H) return;
    int node = warp / H;
    int head = warp - node * H;
    const float* hp  = h + (size_t)node * H * C + head * C;
    const float* asp = a_s + head * C;
    const float* adp = a_d + head * C;
    float s = 0.f, d = 0.f;
    for (int c = lane; c < C; c += 32) {
        float hv = hp[c];
        s += hv * asp[c];
        d += hv * adp[c];
    }
#pragma unroll
    for (int o = 16; o; o >>= 1) {
        s += __shfl_down_sync(0xffffffffu, s, o);
        d += __shfl_down_sync(0xffffffffu, d, o);
    }
    if (lane == 0) {
        as_out[node * H + head] = s;
        ad_out[node * H + head] = d;
    }
}

__device__ __forceinline__ void atomicMaxF(float* addr, float val)
{
    int old = __float_as_int(*addr);
    while (__int_as_float(old) < val) {
        int assumed = old;
        old = atomicCAS((int*)addr, assumed, __float_as_int(val));
        if (old == assumed) break;
    }
}

__device__ __forceinline__ float leaky02(float v)
{
    return v > 0.f ? v : 0.2f * v;
}

__global__ void edge_max_kernel(const int* __restrict__ ei, int E, int n,
                                const float* __restrict__ as,
                                const float* __restrict__ ad,
                                float* __restrict__ m, int H)
{
    int e = blockIdx.x * blockDim.x + threadIdx.x;
    if (e >= E + n) return;
    int s = (e < E) ? ei[e]     : (e - E);
    int d = (e < E) ? ei[E + e] : (e - E);
    for (int h = 0; h < H; h++) {
        float v = leaky02(as[s * H + h] + ad[d * H + h]);
        atomicMaxF(&m[d * H + h], v);
    }
}

__global__ void edge_sum_kernel(const int* __restrict__ ei, int E, int n,
                                const float* __restrict__ as,
                                const float* __restrict__ ad,
                                const float* __restrict__ m,
                                float* __restrict__ den, int H)
{
    int e = blockIdx.x * blockDim.x + threadIdx.x;
    if (e >= E + n) return;
    int s = (e < E) ? ei[e]     : (e - E);
    int d = (e < E) ? ei[E + e] : (e - E);
    for (int h = 0; h < H; h++) {
        float v = leaky02(as[s * H + h] + ad[d * H + h]);
        atomicAdd(&den[d * H + h], __expf(v - m[d * H + h]));
    }
}

__global__ __launch_bounds__(256) void edge_scatter_kernel(
    const int* __restrict__ ei, int E, int n,
    const float* __restrict__ as, const float* __restrict__ ad,
    const float* __restrict__ m, const float* __restrict__ den,
    const float* __restrict__ h, float* __restrict__ acc,
    int H, int C)
{
    int e = blockIdx.x;
    int s = (e < E) ? ei[e]     : (e - E);
    int d = (e < E) ? ei[E + e] : (e - E);

    __shared__ float coef[8];
    if (threadIdx.x < H) {
        int hh = threadIdx.x;
        float v = leaky02(as[s * H + hh] + ad[d * H + hh]);
        coef[hh] = __expf(v - m[d * H + hh]) / (den[d * H + hh] + 1e-16f);
    }
    __syncthreads();

    int HC = H * C;
    const float4* hs = (const float4*)(h + (size_t)s * HC);
    float* ap = acc + (size_t)d * HC;
    for (int i = threadIdx.x; i < HC / 4; i += blockDim.x) {
        float4 v = hs[i];
        float c = coef[(i * 4) >> 8];   // C == 256
        atomicAdd(&ap[i * 4 + 0], v.x * c);
        atomicAdd(&ap[i * 4 + 1], v.y * c);
        atomicAdd(&ap[i * 4 + 2], v.z * c);
        atomicAdd(&ap[i * 4 + 3], v.w * c);
    }
}

__global__ void finalize_cat_kernel(const float* __restrict__ acc,
                                    const float* __restrict__ lin,
                                    const float* __restrict__ b,
                                    const float* __restrict__ lb,
                                    float* __restrict__ out, int n, int HC)
{
    int i = blockIdx.x * blockDim.x + threadIdx.x;
    if (i >= n * HC) return;
    int col = i % HC;
    float v = acc[i] + b[col] + lin[i] + lb[col];
    out[i] = v > 0.f ? v : expm1f(v);
}

__global__ void finalize_mean_kernel(const float* __restrict__ acc,
                                     const float* __restrict__ lin,
                                     const float* __restrict__ b,
                                     const float* __restrict__ lb,
                                     float* __restrict__ out,
                                     int rows, int H, int C)
{
    int i = blockIdx.x * blockDim.x + threadIdx.x;
    if (i >= rows * C) return;
    int nrow = i / C;
    int c = i - nrow * C;
    const float* ap = acc + (size_t)nrow * H * C + c;
    float s = 0.f;
    for (int h = 0; h < H; h++) s += ap[h * C];
    out[i] = s * (1.f / H) + b[c] + lin[(size_t)nrow * C + c] + lb[c];
}

// ------------------------------ host orchestration -------------------------

const int* g_ei_host = nullptr;

static void run_gat_layer(const float* xin, int inCh,
                          const float* W, const float* aS, const float* aD,
                          const float* bias, const float* lw, const float* lb,
                          int H, int C, float* outBuf, bool last,
                          int n, int MP, int E, int rows_out,
                          float* hbuf, float* linbuf, float* accbuf,
                          float* asbuf, float* adbuf, float* mbuf, float* denbuf,
                          __nv_bfloat16* asplit, __nv_bfloat16* bsplitW,
                          __nv_bfloat16* bsplitL)
{
    const int HC = H * C;
    const int linN = last ? C : 1024;
    const int total_e = E + n;
    const int K3 = 3 * inCh;

    convert_A_kernel<<<(MP * inCh + 255) / 256, 256>>>(xin, asplit, n, MP, inCh);
    convert_B_kernel<<<(inCh * HC + 255) / 256, 256>>>(W, bsplitW, inCh, HC);
    convert_B_kernel<<<(inCh * linN + 255) / 256, 256>>>(lw, bsplitL, inCh, linN);

    dim3 g1(HC / BN, MP / BM);
    gemm_bf16_mma_kernel<<<g1, 256, GEMM_SMEM>>>(asplit, bsplitW, hbuf, MP, HC, K3);
    dim3 g2(linN / BN, MP / BM);
    gemm_bf16_mma_kernel<<<g2, 256, GEMM_SMEM>>>(asplit, bsplitL, linbuf, MP, linN, K3);

    alpha_kernel<<<(n * H * 32 + 255) / 256, 256>>>(hbuf, aS, aD, asbuf, adbuf, n, H, C);

    fill_kernel<<<(n * H + 255) / 256, 256>>>(mbuf, -INFINITY, n * H);
    fill_kernel<<<(n * H + 255) / 256, 256>>>(denbuf, 0.f, n * H);
    fill_kernel<<<(n * HC + 255) / 256, 256>>>(accbuf, 0.f, n * HC);

    edge_max_kernel<<<(total_e + 255) / 256, 256>>>(g_ei_host, E, n, asbuf, adbuf, mbuf, H);
    edge_sum_kernel<<<(total_e + 255) / 256, 256>>>(g_ei_host, E, n, asbuf, adbuf, mbuf, denbuf, H);
    edge_scatter_kernel<<<total_e, 256>>>(g_ei_host, E, n, asbuf, adbuf, mbuf, denbuf,
                                          hbuf, accbuf, H, C);

    if (!last) {
        finalize_cat_kernel<<<(n * HC + 255) / 256, 256>>>(accbuf, linbuf, bias, lb, outBuf, n, HC);
    } else {
        finalize_mean_kernel<<<(rows_out * C + 255) / 256, 256>>>(accbuf, linbuf, bias, lb,
                                                                  outBuf, rows_out, H, C);
    }
}

extern "C" void kernel_launch(void* const* d_in, const int* in_sizes, int n_in,
                              void* d_out, int out_size)
{
    const float* x   = (const float*)d_in[0];
    const int*   ei  = (const int*)d_in[1];
    const float* W1  = (const float*)d_in[3];
    const float* as1 = (const float*)d_in[4];
    const float* ad1 = (const float*)d_in[5];
    const float* b1  = (const float*)d_in[6];
    const float* lw1 = (const float*)d_in[7];
    const float* lb1 = (const float*)d_in[8];
    const float* W2  = (const float*)d_in[9];
    const float* as2 = (const float*)d_in[10];
    const float* ad2 = (const float*)d_in[11];
    const float* b2  = (const float*)d_in[12];
    const float* lw2 = (const float*)d_in[13];
    const float* lb2 = (const float*)d_in[14];
    const float* W3  = (const float*)d_in[15];
    const float* as3 = (const float*)d_in[16];
    const float* ad3 = (const float*)d_in[17];
    const float* b3  = (const float*)d_in[18];
    const float* lw3 = (const float*)d_in[19];
    const float* lb3 = (const float*)d_in[20];

    const int n = in_sizes[0] / 512;
    const int E = in_sizes[1] / 2;
    const int rows_out = out_size / 256;
    const int MP = ((n + 127) / 128) * 128;

    g_ei_host = ei;

    cudaFuncSetAttribute(gemm_bf16_mma_kernel,
                         cudaFuncAttributeMaxDynamicSharedMemorySize, GEMM_SMEM);

    float *hbuf, *linbuf, *o1, *o2, *accbuf, *asbuf, *adbuf, *mbuf, *denbuf;
    __nv_bfloat16 *asplit, *bsplitW, *bsplitL;
    cudaGetSymbolAddress((void**)&hbuf,   g_h);
    cudaGetSymbolAddress((void**)&linbuf, g_lin);
    cudaGetSymbolAddress((void**)&o1,     g_o1);
    cudaGetSymbolAddress((void**)&o2,     g_o2);
    cudaGetSymbolAddress((void**)&accbuf, g_acc);
    cudaGetSymbolAddress((void**)&asbuf,  g_as);
    cudaGetSymbolAddress((void**)&adbuf,  g_ad);
    cudaGetSymbolAddress((void**)&mbuf,   g_m);
    cudaGetSymbolAddress((void**)&denbuf, g_den);
    cudaGetSymbolAddress((void**)&asplit,  g_asplit);
    cudaGetSymbolAddress((void**)&bsplitW, g_bsplitW);
    cudaGetSymbolAddress((void**)&bsplitL, g_bsplitL);

    // Layer 1: 512 -> 4x256 concat (1024)
    run_gat_layer(x, 512, W1, as1, ad1, b1, lw1, lb1, 4, 256, o1, false,
                  n, MP, E, rows_out, hbuf, linbuf, accbuf, asbuf, adbuf, mbuf, denbuf,
                  asplit, bsplitW, bsplitL);
    // Layer 2: 1024 -> 4x256 concat (1024)
    run_gat_layer(o1, 1024, W2, as2, ad2, b2, lw2, lb2, 4, 256, o2, false,
                  n, MP, E, rows_out, hbuf, linbuf, accbuf, asbuf, adbuf, mbuf, denbuf,
                  asplit, bsplitW, bsplitL);
    // Layer 3: 1024 -> 6x256 mean (256)
    run_gat_layer(o2, 1024, W3, as3, ad3, b3, lw3, lb3, 6, 256, (float*)d_out, true,
                  n, MP, E, rows_out, hbuf, linbuf, accbuf, asbuf, adbuf, mbuf, denbuf,
                  asplit, bsplitW, bsplitL);
}

// round 4
// speedup vs baseline: 3.1639x; 2.0867x over previous
#include <cuda_runtime.h>
#include <cuda_bf16.h>
#include <math.h>
#include <stdint.h>

// ---------------------------------------------------------------------------
// GAT, 3 layers. GEMMs via mma.sync bf16 (hi/lo split, triple-K compensation).
// Edge softmax+aggregation: CSR pull-mode, one block per dst node, no atomics.
// ---------------------------------------------------------------------------

#define MAXN  20000
#define MAXNP 20096
#define MAXE  340000

__device__ float g_h[MAXNP * 1536];
__device__ float g_lin[MAXNP * 1024];
__device__ float g_o1[MAXN * 1024];
__device__ float g_o2[MAXN * 1024];
__device__ float g_as[MAXN * 6];
__device__ float g_ad[MAXN * 6];

__device__ int g_deg[MAXN];
__device__ int g_off[MAXN + 1];
__device__ int g_cursor[MAXN];
__device__ int g_csr[MAXE];

__device__ __align__(256) __nv_bfloat16 g_asplit[(size_t)MAXNP * 3072];
__device__ __align__(256) __nv_bfloat16 g_bsplitW[1536 * 3072];
__device__ __align__(256) __nv_bfloat16 g_bsplitL[1024 * 3072];

// ------------------------- mma.sync bf16 GEMM ------------------------------
#define BM 128
#define BN 128
#define BKE 64
#define PITCH 72
#define ROWB (PITCH * 2)
#define ASTG (BM * ROWB)
#define BSTG (BN * ROWB)
#define STG  (ASTG + BSTG)
#define NSTG 3
#define GEMM_SMEM (NSTG * STG)

__device__ __forceinline__ uint32_t smem_u32(const void* p) {
    uint32_t a;
    asm("{ .reg .u64 t; cvta.to.shared.u64 t, %1; cvt.u32.u64 %0, t; }"
        : "=r"(a) : "l"(p));
    return a;
}
__device__ __forceinline__ void cp_async16(uint32_t saddr, const void* gptr) {
    asm volatile("cp.async.cg.shared.global [%0], [%1], 16;" :: "r"(saddr), "l"(gptr));
}
__device__ __forceinline__ void cp_commit() {
    asm volatile("cp.async.commit_group;" ::: "memory");
}
template<int NN> __device__ __forceinline__ void cp_wait() {
    asm volatile("cp.async.wait_group %0;" :: "n"(NN) : "memory");
}
__device__ __forceinline__ void ldmA(uint32_t addr, uint32_t& r0, uint32_t& r1,
                                     uint32_t& r2, uint32_t& r3) {
    asm volatile("ldmatrix.sync.aligned.m8n8.x4.shared.b16 {%0,%1,%2,%3}, [%4];"
                 : "=r"(r0), "=r"(r1), "=r"(r2), "=r"(r3) : "r"(addr));
}
__device__ __forceinline__ void ldmB(uint32_t addr, uint32_t& r0, uint32_t& r1) {
    asm volatile("ldmatrix.sync.aligned.m8n8.x2.shared.b16 {%0,%1}, [%2];"
                 : "=r"(r0), "=r"(r1) : "r"(addr));
}
__device__ __forceinline__ void mma16816(float* c, uint32_t a0, uint32_t a1,
                                         uint32_t a2, uint32_t a3,
                                         uint32_t b0, uint32_t b1) {
    asm volatile(
        "mma.sync.aligned.m16n8k16.row.col.f32.bf16.bf16.f32 "
        "{%0,%1,%2,%3}, {%4,%5,%6,%7}, {%8,%9}, {%0,%1,%2,%3};"
        : "+f"(c[0]), "+f"(c[1]), "+f"(c[2]), "+f"(c[3])
        : "r"(a0), "r"(a1), "r"(a2), "r"(a3), "r"(b0), "r"(b1));
}

__global__ __launch_bounds__(256)
void gemm_bf16_mma_kernel(const __nv_bfloat16* __restrict__ A,
                          const __nv_bfloat16* __restrict__ B,
                          float* __restrict__ C, int M, int N, int K)
{
    extern __shared__ char sm[];
    const uint32_t smb = smem_u32(sm);
    const int tid = threadIdx.x;
    const int lane = tid & 31;
    const int wid = tid >> 5;
    const int wm = wid & 1;
    const int wn = wid >> 1;
    const int rowBase = blockIdx.y * BM;
    const int colBase = blockIdx.x * BN;

    float acc[4][4][4];
#pragma unroll
    for (int i = 0; i < 4; i++)
#pragma unroll
        for (int j = 0; j < 4; j++)
#pragma unroll
            for (int v = 0; v < 4; v++) acc[i][j][v] = 0.f;

    const int nk = K / BKE;

    auto issue = [&](int s, int kc) {
        uint32_t aB = smb + s * STG;
        uint32_t bB = aB + ASTG;
#pragma unroll
        for (int g = 0; g < 4; g++) {
            int gi = g * 256 + tid;
            int r = gi >> 3;
            int c = gi & 7;
            const __nv_bfloat16* ga = A + (size_t)(rowBase + r) * K + kc * BKE + c * 8;
            cp_async16(aB + r * ROWB + c * 16, ga);
            const __nv_bfloat16* gb = B + (size_t)(colBase + r) * K + kc * BKE + c * 8;
            cp_async16(bB + r * ROWB + c * 16, gb);
        }
        cp_commit();
    };

#pragma unroll
    for (int s = 0; s < NSTG - 1; s++)
        if (s < nk) issue(s, s);

    const int aRowOff = lane & 15;
    const int aColOff = (lane >> 4) * 16;
    const int bRowOff = lane & 7;
    const int bColOff = ((lane >> 3) & 1) * 16;

    for (int i = 0; i < nk; i++) {
        cp_wait<NSTG - 2>();
        __syncthreads();
        if (i + NSTG - 1 < nk) issue((i + NSTG - 1) % NSTG, i + NSTG - 1);

        uint32_t aB = smb + (i % NSTG) * STG;
        uint32_t bB = aB + ASTG;
#pragma unroll
        for (int ks = 0; ks < 4; ks++) {
            uint32_t a[4][4], b[4][2];
#pragma unroll
            for (int im = 0; im < 4; im++) {
                int row = wm * 64 + im * 16 + aRowOff;
                ldmA(aB + row * ROWB + ks * 32 + aColOff,
                     a[im][0], a[im][1], a[im][2], a[im][3]);
            }
#pragma unroll
            for (int jn = 0; jn < 4; jn++) {
                int row = wn * 32 + jn * 8 + bRowOff;
                ldmB(bB + row * ROWB + ks * 32 + bColOff, b[jn][0], b[jn][1]);
            }
#pragma unroll
            for (int im = 0; im < 4; im++)
#pragma unroll
                for (int jn = 0; jn < 4; jn++)
                    mma16816(acc[im][jn], a[im][0], a[im][1], a[im][2], a[im][3],
                             b[jn][0], b[jn][1]);
        }
        __syncthreads();
    }

    const int q = lane >> 2;
    const int qc = (lane & 3) * 2;
#pragma unroll
    for (int im = 0; im < 4; im++) {
        int r0 = rowBase + wm * 64 + im * 16 + q;
#pragma unroll
        for (int jn = 0; jn < 4; jn++) {
            int col = colBase + wn * 32 + jn * 8 + qc;
            float* p0 = C + (size_t)r0 * N + col;
            float* p1 = C + (size_t)(r0 + 8) * N + col;
            p0[0] = acc[im][jn][0]; p0[1] = acc[im][jn][1];
            p1[0] = acc[im][jn][2]; p1[1] = acc[im][jn][3];
        }
    }
}

// ---------------------- split-bf16 conversion kernels ----------------------
__global__ void convert_A_kernel(const float* __restrict__ x,
                                 __nv_bfloat16* __restrict__ out,
                                 int n, int MP, int K)
{
    int idx = blockIdx.x * blockDim.x + threadIdx.x;
    if (idx >= MP * K) return;
    int row = idx / K;
    int k = idx - row * K;
    float a = (row < n) ? x[(size_t)row * K + k] : 0.f;
    __nv_bfloat16 hi = __float2bfloat16(a);
    __nv_bfloat16 lo = __float2bfloat16(a - __bfloat162float(hi));
    size_t base = (size_t)row * (3 * K);
    out[base + k] = hi;
    out[base + K + k] = lo;
    out[base + 2 * K + k] = hi;
}

__global__ void convert_B_kernel(const float* __restrict__ Bsrc,
                                 __nv_bfloat16* __restrict__ out,
                                 int K, int Nout)
{
    int idx = blockIdx.x * blockDim.x + threadIdx.x;
    if (idx >= K * Nout) return;
    int k = idx / Nout;
    int nn = idx - k * Nout;
    float b = Bsrc[(size_t)k * Nout + nn];
    __nv_bfloat16 hi = __float2bfloat16(b);
    __nv_bfloat16 lo = __float2bfloat16(b - __bfloat162float(hi));
    size_t base = (size_t)nn * (3 * K);
    out[base + k] = hi;
    out[base + K + k] = hi;
    out[base + 2 * K + k] = lo;
}

// ---------------------------- CSR construction -----------------------------
__global__ void zero_int_kernel(int* __restrict__ p, int n)
{
    int i = blockIdx.x * blockDim.x + threadIdx.x;
    if (i < n) p[i] = 0;
}

__global__ void hist_kernel(const int* __restrict__ ei, int E, int n,
                            int* __restrict__ deg)
{
    int i = blockIdx.x * blockDim.x + threadIdx.x;
    if (i >= E + n) return;
    int d = (i < E) ? ei[E + i] : (i - E);
    atomicAdd(&deg[d], 1);
}

__global__ __launch_bounds__(1024) void scan_kernel(const int* __restrict__ deg,
                                                    int* __restrict__ off,
                                                    int* __restrict__ cursor, int n)
{
    __shared__ int partial[1024];
    const int t = threadIdx.x;
    const int per = (n + 1023) / 1024;
    const int s0 = t * per;
    int s = 0;
    for (int i = 0; i < per; i++) {
        int idx = s0 + i;
        if (idx < n) s += deg[idx];
    }
    partial[t] = s;
    __syncthreads();
    for (int o = 1; o < 1024; o <<= 1) {
        int v = (t >= o) ? partial[t - o] : 0;
        __syncthreads();
        partial[t] += v;
        __syncthreads();
    }
    int base = (t == 0) ? 0 : partial[t - 1];
    for (int i = 0; i < per; i++) {
        int idx = s0 + i;
        if (idx < n) {
            off[idx] = base;
            cursor[idx] = base;
            base += deg[idx];
        }
    }
    if (t == 1023) off[n] = partial[1023];
}

__global__ void csr_scatter_kernel(const int* __restrict__ ei, int E, int n,
                                   int* __restrict__ cursor,
                                   int* __restrict__ csr)
{
    int i = blockIdx.x * blockDim.x + threadIdx.x;
    if (i >= E + n) return;
    int s = (i < E) ? ei[i]     : (i - E);
    int d = (i < E) ? ei[E + i] : (i - E);
    int slot = atomicAdd(&cursor[d], 1);
    csr[slot] = s;
}

// -------------------------- attention logits -------------------------------
__global__ void alpha_kernel(const float* __restrict__ h,
                             const float* __restrict__ a_s,
                             const float* __restrict__ a_d,
                             float* __restrict__ as_out,
                             float* __restrict__ ad_out,
                             int n, int H, int C)
{
    int warp = (blockIdx.x * blockDim.x + threadIdx.x) >> 5;
    int lane = threadIdx.x & 31;
    if (warp >= n * H) return;
    int node = warp / H;
    int head = warp - node * H;
    const float* hp  = h + (size_t)node * H * C + head * C;
    const float* asp = a_s + head * C;
    const float* adp = a_d + head * C;
    float s = 0.f, d = 0.f;
    for (int c = lane; c < C; c += 32) {
        float hv = hp[c];
        s += hv * asp[c];
        d += hv * adp[c];
    }
#pragma unroll
    for (int o = 16; o; o >>= 1) {
        s += __shfl_down_sync(0xffffffffu, s, o);
        d += __shfl_down_sync(0xffffffffu, d, o);
    }
    if (lane == 0) {
        as_out[node * H + head] = s;
        ad_out[node * H + head] = d;
    }
}

// --------------------- CSR pull-mode aggregation ---------------------------
// One block per dst node. H heads of 256 channels. Thread handles 4 channels.
// MODE 0: out = elu(agg + b + lin + lb), all heads concat (blockDim = H*64).
// MODE 1: out = mean_heads(agg) + b + lin + lb   (blockDim = H*64, C=256 out).
#define CHUNK 64

template<int H, int MODE>
__global__ __launch_bounds__(H * 64) void gat_agg_kernel(
    const int* __restrict__ csr, const int* __restrict__ off,
    const float* __restrict__ as, const float* __restrict__ ad,
    const float* __restrict__ h,
    const float* __restrict__ lin,
    const float* __restrict__ bias, const float* __restrict__ lb,
    float* __restrict__ out)
{
    constexpr int HC = H * 256;
    const int d = blockIdx.x;
    const int tid = threadIdx.x;
    const int lane = tid & 31;
    const int start = off[d];
    const int end = off[d + 1];

    __shared__ float s_m[H], s_den[H];
    __shared__ int   s_src[CHUNK];
    __shared__ float s_coef[CHUNK * H];
    __shared__ float s_red[MODE ? HC : 1];

    if (tid < 32) {
        float adv[H], lm[H], ld_[H];
#pragma unroll
        for (int hh = 0; hh < H; hh++) {
            adv[hh] = ad[d * H + hh];
            lm[hh] = -INFINITY;
            ld_[hh] = 0.f;
        }
        for (int e = start + lane; e < end; e += 32) {
            int s = csr[e];
#pragma unroll
            for (int hh = 0; hh < H; hh++) {
                float v = as[s * H + hh] + adv[hh];
                v = v > 0.f ? v : 0.2f * v;
                lm[hh] = fmaxf(lm[hh], v);
            }
        }
#pragma unroll
        for (int hh = 0; hh < H; hh++)
#pragma unroll
            for (int o = 16; o; o >>= 1)
                lm[hh] = fmaxf(lm[hh], __shfl_xor_sync(0xffffffffu, lm[hh], o));
        for (int e = start + lane; e < end; e += 32) {
            int s = csr[e];
#pragma unroll
            for (int hh = 0; hh < H; hh++) {
                float v = as[s * H + hh] + adv[hh];
                v = v > 0.f ? v : 0.2f * v;
                ld_[hh] += __expf(v - lm[hh]);
            }
        }
#pragma unroll
        for (int hh = 0; hh < H; hh++)
#pragma unroll
            for (int o = 16; o; o >>= 1)
                ld_[hh] += __shfl_xor_sync(0xffffffffu, ld_[hh], o);
        if (lane == 0) {
#pragma unroll
            for (int hh = 0; hh < H; hh++) {
                s_m[hh] = lm[hh];
                s_den[hh] = 1.f / (ld_[hh] + 1e-16f);
            }
        }
    }
    __syncthreads();

    const int c0 = tid * 4;
    const int myhead = c0 >> 8;
    float a0 = 0.f, a1 = 0.f, a2 = 0.f, a3 = 0.f;

    for (int base = start; base < end; base += CHUNK) {
        const int cnt = min(CHUNK, end - base);
        if (tid < 32) {
            for (int i = lane; i < cnt; i += 32) {
                int s = csr[base + i];
                s_src[i] = s;
#pragma unroll
                for (int hh = 0; hh < H; hh++) {
                    float v = as[s * H + hh] + ad[d * H + hh];
                    v = v > 0.f ? v : 0.2f * v;
                    s_coef[i * H + hh] = __expf(v - s_m[hh]) * s_den[hh];
                }
            }
        }
        __syncthreads();
#pragma unroll 4
        for (int i = 0; i < cnt; i++) {
            int s = s_src[i];
            float cf = s_coef[i * H + myhead];
            const float4 v = *(const float4*)&h[(size_t)s * HC + c0];
            a0 += v.x * cf; a1 += v.y * cf; a2 += v.z * cf; a3 += v.w * cf;
        }
        __syncthreads();
    }

    if (MODE == 0) {
        float4 bb = make_float4(bias[c0] + lb[c0], bias[c0 + 1] + lb[c0 + 1],
                                bias[c0 + 2] + lb[c0 + 2], bias[c0 + 3] + lb[c0 + 3]);
        const float4 lv = *(const float4*)&lin[(size_t)d * HC + c0];
        float r0 = a0 + bb.x + lv.x, r1 = a1 + bb.y + lv.y;
        float r2 = a2 + bb.z + lv.z, r3 = a3 + bb.w + lv.w;
        r0 = r0 > 0.f ? r0 : expm1f(r0);
        r1 = r1 > 0.f ? r1 : expm1f(r1);
        r2 = r2 > 0.f ? r2 : expm1f(r2);
        r3 = r3 > 0.f ? r3 : expm1f(r3);
        *(float4*)&out[(size_t)d * HC + c0] = make_float4(r0, r1, r2, r3);
    } else {
        s_red[c0] = a0; s_red[c0 + 1] = a1; s_red[c0 + 2] = a2; s_red[c0 + 3] = a3;
        __syncthreads();
        if (tid < 64) {
            int j0 = tid * 4;
#pragma unroll
            for (int j = j0; j < j0 + 4; j++) {
                float s = 0.f;
#pragma unroll
                for (int hh = 0; hh < H; hh++) s += s_red[j + hh * 256];
                out[(size_t)d * 256 + j] = s * (1.f / H) + bias[j]
                                         + lin[(size_t)d * 256 + j] + lb[j];
            }
        }
    }
}

// ------------------------------ host orchestration -------------------------

extern "C" void kernel_launch(void* const* d_in, const int* in_sizes, int n_in,
                              void* d_out, int out_size)
{
    const float* x   = (const float*)d_in[0];
    const int*   ei  = (const int*)d_in[1];
    const float* W1  = (const float*)d_in[3];
    const float* as1 = (const float*)d_in[4];
    const float* ad1 = (const float*)d_in[5];
    const float* b1  = (const float*)d_in[6];
    const float* lw1 = (const float*)d_in[7];
    const float* lb1 = (const float*)d_in[8];
    const float* W2  = (const float*)d_in[9];
    const float* as2 = (const float*)d_in[10];
    const float* ad2 = (const float*)d_in[11];
    const float* b2  = (const float*)d_in[12];
    const float* lw2 = (const float*)d_in[13];
    const float* lb2 = (const float*)d_in[14];
    const float* W3  = (const float*)d_in[15];
    const float* as3 = (const float*)d_in[16];
    const float* ad3 = (const float*)d_in[17];
    const float* b3  = (const float*)d_in[18];
    const float* lw3 = (const float*)d_in[19];
    const float* lb3 = (const float*)d_in[20];

    const int n = in_sizes[0] / 512;
    const int E = in_sizes[1] / 2;
    const int rows_out = out_size / 256;
    const int MP = ((n + 127) / 128) * 128;
    const int total_e = E + n;

    cudaFuncSetAttribute(gemm_bf16_mma_kernel,
                         cudaFuncAttributeMaxDynamicSharedMemorySize, GEMM_SMEM);

    float *hbuf, *linbuf, *o1, *o2, *asbuf, *adbuf;
    int *deg, *off, *cursor, *csr;
    __nv_bfloat16 *asplit, *bsplitW, *bsplitL;
    cudaGetSymbolAddress((void**)&hbuf,   g_h);
    cudaGetSymbolAddress((void**)&linbuf, g_lin);
    cudaGetSymbolAddress((void**)&o1,     g_o1);
    cudaGetSymbolAddress((void**)&o2,     g_o2);
    cudaGetSymbolAddress((void**)&asbuf,  g_as);
    cudaGetSymbolAddress((void**)&adbuf,  g_ad);
    cudaGetSymbolAddress((void**)&deg,    g_deg);
    cudaGetSymbolAddress((void**)&off,    g_off);
    cudaGetSymbolAddress((void**)&cursor, g_cursor);
    cudaGetSymbolAddress((void**)&csr,    g_csr);
    cudaGetSymbolAddress((void**)&asplit,  g_asplit);
    cudaGetSymbolAddress((void**)&bsplitW, g_bsplitW);
    cudaGetSymbolAddress((void**)&bsplitL, g_bsplitL);

    // ---- CSR build (once per call) ----
    zero_int_kernel<<<(n + 255) / 256, 256>>>(deg, n);
    hist_kernel<<<(total_e + 255) / 256, 256>>>(ei, E, n, deg);
    scan_kernel<<<1, 1024>>>(deg, off, cursor, n);
    csr_scatter_kernel<<<(total_e + 255) / 256, 256>>>(ei, E, n, cursor, csr);

    struct Layer {
        const float* W; const float* aS; const float* aD; const float* b;
        const float* lw; const float* lb; int H; int inCh; bool last;
        const float* xin; float* out;
    };
    Layer layers[3] = {
        { W1, as1, ad1, b1, lw1, lb1, 4, 512,  false, x,  o1 },
        { W2, as2, ad2, b2, lw2, lb2, 4, 1024, false, o1, o2 },
        { W3, as3, ad3, b3, lw3, lb3, 6, 1024, true,  o2, (float*)d_out },
    };

    for (int L = 0; L < 3; L++) {
        const Layer& ly = layers[L];
        const int HC = ly.H * 256;
        const int linN = ly.last ? 256 : 1024;
        const int K3 = 3 * ly.inCh;

        convert_A_kernel<<<(MP * ly.inCh + 255) / 256, 256>>>(ly.xin, asplit, n, MP, ly.inCh);
        convert_B_kernel<<<(ly.inCh * HC + 255) / 256, 256>>>(ly.W, bsplitW, ly.inCh, HC);
        convert_B_kernel<<<(ly.inCh * linN + 255) / 256, 256>>>(ly.lw, bsplitL, ly.inCh, linN);

        dim3 g1(HC / BN, MP / BM);
        gemm_bf16_mma_kernel<<<g1, 256, GEMM_SMEM>>>(asplit, bsplitW, hbuf, MP, HC, K3);
        dim3 g2(linN / BN, MP / BM);
        gemm_bf16_mma_kernel<<<g2, 256, GEMM_SMEM>>>(asplit, bsplitL, linbuf, MP, linN, K3);

        alpha_kernel<<<(n * ly.H * 32 + 255) / 256, 256>>>(hbuf, ly.aS, ly.aD,
                                                           asbuf, adbuf, n, ly.H, 256);

        if (!ly.last) {
            gat_agg_kernel<4, 0><<<n, 256>>>(csr, off, asbuf, adbuf, hbuf,
                                             linbuf, ly.b, ly.lb, ly.out);
        } else {
            gat_agg_kernel<6, 1><<<rows_out, 384>>>(csr, off, asbuf, adbuf, hbuf,
                                                    linbuf, ly.b, ly.lb, ly.out);
        }
    }
}